// round 5
// baseline (speedup 1.0000x reference)
#include <cuda_runtime.h>
#include <math.h>
#include <stdint.h>

#define CC   192
#define C3   576
#define NB   2
#define NHD  4
#define HD   48
#define HH   256
#define WW   256
#define HWN  65536

// Scratch (device globals — allocation-free rule)
__device__ float g_qkv1[(size_t)NB * C3 * HWN];     // after 1x1 qkv conv
__device__ float g_qkv2[(size_t)NB * C3 * HWN];     // after depthwise 3x3
__device__ float g_attout[(size_t)NB * CC * HWN];   // attention output (pre-proj)
__device__ float g_gram[NB * NHD * HD * HD];        // raw q.k^T accumulators
__device__ float g_attn[NB * NHD * HD * HD];        // softmaxed attention
__device__ float g_sumsq[NB * 2 * CC];              // sum-of-squares q then k

// ---------------------------------------------------------------------------
__global__ void zero_kernel() {
    int i = blockIdx.x * blockDim.x + threadIdx.x;
    if (i < NB * NHD * HD * HD) g_gram[i] = 0.f;
    if (i < NB * 2 * CC)        g_sumsq[i] = 0.f;
}
// no-op slot-shifter so ncu's fixed capture slot (launch #4) lands on dwconv
__global__ void dummy_kernel() {}

// ---------------------------------------------------------------------------
// TF32 tensor-core GEMM: C[M,N] = A[M,K] * B[K,N]; batched over z on B and C.
// Block tile 128x256, BK=16, 8 warps (2x4), warp tile 64x64, mma m16n8k8.
// LDS-per-MMA ratio = 1.0 (vs 1.5 before): crossbar-bound fix.
__device__ __forceinline__ uint32_t f2tf32(float f) {
    uint32_t u;
    asm("cvt.rna.tf32.f32 %0, %1;" : "=r"(u) : "f"(f));
    return u;
}

__device__ __forceinline__ void mma_tf32(float* c, const uint32_t* a, const uint32_t* b) {
    asm volatile(
        "mma.sync.aligned.m16n8k8.row.col.f32.tf32.tf32.f32 "
        "{%0,%1,%2,%3}, {%4,%5,%6,%7}, {%8,%9}, {%0,%1,%2,%3};"
        : "+f"(c[0]), "+f"(c[1]), "+f"(c[2]), "+f"(c[3])
        : "r"(a[0]), "r"(a[1]), "r"(a[2]), "r"(a[3]), "r"(b[0]), "r"(b[1]));
}

#define TBM 128
#define TBN 256
#define TBK 16
#define ASTR 20     // As row stride (words): frag loads hit 32 distinct banks
#define BSTR 264    // Bs row stride (words): 264%32=8 -> frag loads conflict-free
#define AS_WORDS (TBM * ASTR)   // 2560
#define BS_WORDS (TBK * BSTR)   // 4224
#define SMEM_WORDS (2 * AS_WORDS + 2 * BS_WORDS)   // 13568 words = 54272 B

__global__ void __launch_bounds__(256, 1)
tf32_gemm(const float* __restrict__ A, const float* __restrict__ B,
          float* __restrict__ C, int M, int N, int K,
          size_t strideB, size_t strideC) {
    extern __shared__ uint32_t sm[];
    uint32_t* AsBuf[2] = { sm, sm + AS_WORDS };
    uint32_t* BsBuf[2] = { sm + 2 * AS_WORDS, sm + 2 * AS_WORDS + BS_WORDS };

    const float* Bp = B + (size_t)blockIdx.z * strideB;
    float*       Cp = C + (size_t)blockIdx.z * strideC;

    int tid = threadIdx.x, lane = tid & 31, warp = tid >> 5;
    int wm = warp >> 2, wn = warp & 3;          // 2 warps in M, 4 in N
    int mBase = blockIdx.y * TBM, nBase = blockIdx.x * TBN;

    // loader assignments
    int arow = tid >> 1, akc = (tid & 1) * 8;   // A: 128 rows x 16 k
    int bkk  = tid >> 4, bn  = (tid & 15) * 16; // B: 16 k x 256 n

    float4 aR0, aR1, bR[4];

    auto ldg = [&](int k0) {
        int gr = mBase + arow;
        if (gr < M) {
            aR0 = *(const float4*)(A + (size_t)gr * K + k0 + akc);
            aR1 = *(const float4*)(A + (size_t)gr * K + k0 + akc + 4);
        } else {
            aR0 = make_float4(0.f, 0.f, 0.f, 0.f);
            aR1 = aR0;
        }
        const float* bp = Bp + (size_t)(k0 + bkk) * N + nBase + bn;
        #pragma unroll
        for (int c = 0; c < 4; c++) bR[c] = *(const float4*)(bp + c * 4);
    };
    auto sts = [&](int buf) {
        uint32_t* ap = AsBuf[buf] + arow * ASTR + akc;
        ap[0] = f2tf32(aR0.x); ap[1] = f2tf32(aR0.y);
        ap[2] = f2tf32(aR0.z); ap[3] = f2tf32(aR0.w);
        ap[4] = f2tf32(aR1.x); ap[5] = f2tf32(aR1.y);
        ap[6] = f2tf32(aR1.z); ap[7] = f2tf32(aR1.w);
        uint32_t* bq = BsBuf[buf] + bkk * BSTR + bn;
        #pragma unroll
        for (int c = 0; c < 4; c++) {
            bq[c * 4 + 0] = f2tf32(bR[c].x); bq[c * 4 + 1] = f2tf32(bR[c].y);
            bq[c * 4 + 2] = f2tf32(bR[c].z); bq[c * 4 + 3] = f2tf32(bR[c].w);
        }
    };

    float acc[4][8][4] = {};

    auto compute = [&](int buf) {
        const uint32_t* As = AsBuf[buf];
        const uint32_t* Bs = BsBuf[buf];
        #pragma unroll
        for (int k8 = 0; k8 < 2; k8++) {
            uint32_t a[4][4], b[8][2];
            #pragma unroll
            for (int mi = 0; mi < 4; mi++) {
                int r = wm * 64 + mi * 16 + (lane >> 2);
                int c = k8 * 8 + (lane & 3);
                a[mi][0] = As[r * ASTR + c];
                a[mi][1] = As[(r + 8) * ASTR + c];
                a[mi][2] = As[r * ASTR + c + 4];
                a[mi][3] = As[(r + 8) * ASTR + c + 4];
            }
            #pragma unroll
            for (int ni = 0; ni < 8; ni++) {
                int kk = k8 * 8 + (lane & 3);
                int n = wn * 64 + ni * 8 + (lane >> 2);
                b[ni][0] = Bs[kk * BSTR + n];
                b[ni][1] = Bs[(kk + 4) * BSTR + n];
            }
            #pragma unroll
            for (int mi = 0; mi < 4; mi++)
                #pragma unroll
                for (int ni = 0; ni < 8; ni++)
                    mma_tf32(acc[mi][ni], a[mi], b[ni]);
        }
    };

    int nk = K / TBK;
    ldg(0);
    sts(0);
    __syncthreads();
    for (int kt = 0; kt < nk; kt++) {
        if (kt + 1 < nk) ldg((kt + 1) * TBK);
        compute(kt & 1);
        if (kt + 1 < nk) sts((kt + 1) & 1);
        __syncthreads();
    }

    // epilogue
    #pragma unroll
    for (int mi = 0; mi < 4; mi++) {
        int r0 = mBase + wm * 64 + mi * 16 + (lane >> 2);
        #pragma unroll
        for (int ni = 0; ni < 8; ni++) {
            int col = nBase + wn * 64 + ni * 8 + (lane & 3) * 2;
            if (r0 < M)
                *(float2*)(Cp + (size_t)r0 * N + col) =
                    make_float2(acc[mi][ni][0], acc[mi][ni][1]);
            if (r0 + 8 < M)
                *(float2*)(Cp + (size_t)(r0 + 8) * N + col) =
                    make_float2(acc[mi][ni][2], acc[mi][ni][3]);
        }
    }
}

// ---------------------------------------------------------------------------
// Depthwise 3x3, pad 1 (cross-correlation). 4 outputs/thread, float4 I/O.
// Fused: per-channel sum-of-squares for q/k channels (replaces rownorm pass).
__global__ void dwconv_kernel(const float* __restrict__ w) {
    size_t t = (size_t)blockIdx.x * blockDim.x + threadIdx.x;  // per 4 outputs
    int x4 = (int)(t & 63) * 4;
    int y  = (int)((t >> 6) & (HH - 1));
    size_t plane = t >> 14;              // b*C3 + ch  (one plane per block)
    int ch = (int)(plane % C3);
    int b  = (int)(plane / C3);
    const float* in = g_qkv1 + plane * HWN;
    const float* wp = w + ch * 9;
    float acc0 = 0.f, acc1 = 0.f, acc2 = 0.f, acc3 = 0.f;
    #pragma unroll
    for (int dy = 0; dy < 3; dy++) {
        int yy = y + dy - 1;
        if (yy < 0 || yy >= HH) continue;
        const float* rp = in + yy * WW + x4;
        float4 c = *(const float4*)rp;
        float left  = (x4 > 0)      ? rp[-1] : 0.f;
        float right = (x4 + 4 < WW) ? rp[4]  : 0.f;
        float w0 = wp[dy * 3], w1 = wp[dy * 3 + 1], w2 = wp[dy * 3 + 2];
        acc0 += w0 * left + w1 * c.x + w2 * c.y;
        acc1 += w0 * c.x  + w1 * c.y + w2 * c.z;
        acc2 += w0 * c.y  + w1 * c.z + w2 * c.w;
        acc3 += w0 * c.z  + w1 * c.w + w2 * right;
    }
    *(float4*)(g_qkv2 + plane * HWN + y * WW + x4) =
        make_float4(acc0, acc1, acc2, acc3);

    // fused per-channel sum of squares (q and k channels only)
    __shared__ float red[256];
    red[threadIdx.x] = acc0 * acc0 + acc1 * acc1 + acc2 * acc2 + acc3 * acc3;
    __syncthreads();
    for (int s = 128; s > 0; s >>= 1) {
        if (threadIdx.x < s) red[threadIdx.x] += red[threadIdx.x + s];
        __syncthreads();
    }
    if (threadIdx.x == 0 && ch < 2 * CC)
        atomicAdd(&g_sumsq[b * 2 * CC + ch], red[0]);
}

// ---------------------------------------------------------------------------
#define GK 64
#define GSPAN 4096
__global__ void gram_kernel() {
    int bh = blockIdx.y;
    int b = bh >> 2, h = bh & 3;
    const float* qb = g_qkv2 + ((size_t)b * C3 + h * HD) * HWN;
    const float* kb = g_qkv2 + ((size_t)b * C3 + CC + h * HD) * HWN;

    __shared__ float qs[GK][HD + 1];
    __shared__ float ks[GK][HD + 1];

    int tid = threadIdx.x;
    int tx = tid & 15, ty = tid >> 4;
    float acc[3][3] = {};

    int n0 = blockIdx.x * GSPAN;
    for (int nc = 0; nc < GSPAN; nc += GK) {
        int nb = n0 + nc;
        for (int i = tid; i < HD * GK; i += 256) {
            int kk = i & (GK - 1);
            int c  = i >> 6;
            qs[kk][c] = qb[(size_t)c * HWN + nb + kk];
            ks[kk][c] = kb[(size_t)c * HWN + nb + kk];
        }
        __syncthreads();
        #pragma unroll 8
        for (int kk = 0; kk < GK; kk++) {
            float qv[3], kv[3];
            #pragma unroll
            for (int i = 0; i < 3; i++) qv[i] = qs[kk][ty + 16 * i];
            #pragma unroll
            for (int j = 0; j < 3; j++) kv[j] = ks[kk][tx + 16 * j];
            #pragma unroll
            for (int i = 0; i < 3; i++)
                #pragma unroll
                for (int j = 0; j < 3; j++)
                    acc[i][j] += qv[i] * kv[j];
        }
        __syncthreads();
    }
    #pragma unroll
    for (int i = 0; i < 3; i++)
        #pragma unroll
        for (int j = 0; j < 3; j++)
            atomicAdd(&g_gram[((size_t)bh * HD + ty + 16 * i) * HD + tx + 16 * j],
                      acc[i][j]);
}

// ---------------------------------------------------------------------------
__global__ void attn_kernel(const float* __restrict__ temp) {
    int r = blockIdx.x * blockDim.x + threadIdx.x;
    if (r >= NB * NHD * HD) return;
    int b = r / (NHD * HD);
    int h = (r / HD) % NHD;
    int c = r % HD;
    float nq = fmaxf(sqrtf(g_sumsq[b * 2 * CC + h * HD + c]), 1e-12f);
    const float* gr = g_gram + (size_t)((b * NHD + h) * HD + c) * HD;
    float t = temp[h];
    float a[HD];
    float mx = -1e30f;
    for (int d = 0; d < HD; d++) {
        float nk = fmaxf(sqrtf(g_sumsq[b * 2 * CC + CC + h * HD + d]), 1e-12f);
        float v = gr[d] / (nq * nk) * t;
        a[d] = v;
        mx = fmaxf(mx, v);
    }
    float sum = 0.f;
    for (int d = 0; d < HD; d++) { a[d] = expf(a[d] - mx); sum += a[d]; }
    float inv = 1.f / sum;
    float* o = g_attn + (size_t)((b * NHD + h) * HD + c) * HD;
    for (int d = 0; d < HD; d++) o[d] = a[d] * inv;
}

// ---------------------------------------------------------------------------
__global__ void av_kernel() {
    int bh = blockIdx.y;
    int b = bh >> 2, h = bh & 3;
    __shared__ float sa[HD * HD];
    for (int i = threadIdx.x; i < HD * HD; i += 256)
        sa[i] = g_attn[(size_t)bh * HD * HD + i];
    __syncthreads();
    int n = blockIdx.x * 256 + threadIdx.x;
    const float* vb = g_qkv2 + ((size_t)b * C3 + 2 * CC + h * HD) * HWN + n;
    float*       ob = g_attout + ((size_t)b * CC + h * HD) * HWN + n;
    float acc[HD];
    #pragma unroll
    for (int c = 0; c < HD; c++) acc[c] = 0.f;
    #pragma unroll 4
    for (int d = 0; d < HD; d++) {
        float v = vb[(size_t)d * HWN];
        #pragma unroll
        for (int c = 0; c < HD; c++) acc[c] += sa[c * HD + d] * v;
    }
    #pragma unroll
    for (int c = 0; c < HD; c++) ob[(size_t)c * HWN] = acc[c];
}

// ---------------------------------------------------------------------------
extern "C" void kernel_launch(void* const* d_in, const int* in_sizes, int n_in,
                              void* d_out, int out_size) {
    const float* x      = (const float*)d_in[0];
    const float* qkv_w  = (const float*)d_in[1];
    const float* dw_w   = (const float*)d_in[2];
    const float* proj_w = (const float*)d_in[3];
    const float* temp   = (const float*)d_in[4];
    float* out = (float*)d_out;

    float *qkv1, *attout;
    cudaGetSymbolAddress((void**)&qkv1,   g_qkv1);
    cudaGetSymbolAddress((void**)&attout, g_attout);

    cudaFuncSetAttribute(tf32_gemm, cudaFuncAttributeMaxDynamicSharedMemorySize,
                         SMEM_WORDS * 4);

    // launch 1
    zero_kernel<<<(NB * NHD * HD * HD + 255) / 256, 256>>>();

    // launch 2: qkv = qkv_w @ x : [576,192] x [192,65536] per batch
    tf32_gemm<<<dim3(HWN / TBN, (C3 + TBM - 1) / TBM, NB), 256, SMEM_WORDS * 4>>>(
        qkv_w, x, qkv1, C3, HWN, CC, (size_t)CC * HWN, (size_t)C3 * HWN);

    // launch 3: slot shim so ncu captures dwconv (launch #4)
    dummy_kernel<<<1, 1>>>();

    // launch 4: dwconv (+ fused q/k sum-of-squares)
    dwconv_kernel<<<(int)(((size_t)NB * C3 * HWN) / 4 / 256), 256>>>(dw_w);

    gram_kernel<<<dim3(HWN / GSPAN, NB * NHD), 256>>>();

    attn_kernel<<<2, 192>>>(temp);

    av_kernel<<<dim3(HWN / 256, NB * NHD), 256>>>();

    // final = proj_w @ attout : [192,192] x [192,65536] per batch
    tf32_gemm<<<dim3(HWN / TBN, (CC + TBM - 1) / TBM, NB), 256, SMEM_WORDS * 4>>>(
        proj_w, attout, out, CC, HWN, CC, (size_t)CC * HWN, (size_t)CC * HWN);
}

// round 7
// speedup vs baseline: 1.5908x; 1.5908x over previous
#include <cuda_runtime.h>
#include <math.h>
#include <stdint.h>

#define CC   192
#define C3   576
#define NB   2
#define NHD  4
#define HD   48
#define HH   256
#define WW   256
#define HWN  65536

// Scratch (device globals — allocation-free rule)
__device__ float g_qkv1[(size_t)NB * C3 * HWN];     // after 1x1 qkv conv
__device__ float g_qkv2[(size_t)NB * C3 * HWN];     // after depthwise 3x3
__device__ float g_attout[(size_t)NB * CC * HWN];   // attention output (pre-proj)
__device__ float g_gram[NB * NHD * HD * HD];        // raw q.k^T accumulators
__device__ float g_attn[NB * NHD * HD * HD];        // softmaxed attention
__device__ float g_norms[NB * 2 * CC];              // L2 norms q, then k

// ---------------------------------------------------------------------------
__global__ void zero_kernel() {
    int i = blockIdx.x * blockDim.x + threadIdx.x;
    if (i < NB * NHD * HD * HD) g_gram[i] = 0.f;
}

// ---------------------------------------------------------------------------
// TF32 tensor-core GEMM (R4 proven config): block 128x128, BK=16, 8 warps,
// warp tile 32x64, occ 2.
__device__ __forceinline__ uint32_t f2tf32(float f) {
    uint32_t u;
    asm("cvt.rna.tf32.f32 %0, %1;" : "=r"(u) : "f"(f));
    return u;
}

__device__ __forceinline__ void mma_tf32(float* c, const uint32_t* a, const uint32_t* b) {
    asm volatile(
        "mma.sync.aligned.m16n8k8.row.col.f32.tf32.tf32.f32 "
        "{%0,%1,%2,%3}, {%4,%5,%6,%7}, {%8,%9}, {%0,%1,%2,%3};"
        : "+f"(c[0]), "+f"(c[1]), "+f"(c[2]), "+f"(c[3])
        : "r"(a[0]), "r"(a[1]), "r"(a[2]), "r"(a[3]), "r"(b[0]), "r"(b[1]));
}

#define TBM 128
#define TBN 128
#define TBK 16
#define ASTR 20
#define BSTR 136

__global__ void __launch_bounds__(256, 2)
tf32_gemm(const float* __restrict__ A, const float* __restrict__ B,
          float* __restrict__ C, int M, int N, int K,
          size_t strideB, size_t strideC) {
    const float* Bp = B + (size_t)blockIdx.z * strideB;
    float*       Cp = C + (size_t)blockIdx.z * strideC;

    __shared__ uint32_t As[2][TBM * ASTR];
    __shared__ uint32_t Bs[2][TBK * BSTR];

    int tid = threadIdx.x, lane = tid & 31, warp = tid >> 5;
    int wm = warp >> 1, wn = warp & 1;
    int mBase = blockIdx.y * TBM, nBase = blockIdx.x * TBN;

    float4 aReg[2], bReg[2];

    auto ldg = [&](int k0) {
        #pragma unroll
        for (int s = 0; s < 2; s++) {
            int j = tid + 256 * s;
            int row = j >> 2, kc = (j & 3) << 2;
            int gr = mBase + row;
            if (gr < M) aReg[s] = *(const float4*)(A + (size_t)gr * K + k0 + kc);
            else        aReg[s] = make_float4(0.f, 0.f, 0.f, 0.f);
            int kk = j >> 5, n4 = (j & 31) << 2;
            bReg[s] = *(const float4*)(Bp + (size_t)(k0 + kk) * N + nBase + n4);
        }
    };
    auto sts = [&](int buf) {
        #pragma unroll
        for (int s = 0; s < 2; s++) {
            int j = tid + 256 * s;
            int row = j >> 2, kc = (j & 3) << 2;
            uint32_t* p = &As[buf][row * ASTR + kc];
            p[0] = f2tf32(aReg[s].x); p[1] = f2tf32(aReg[s].y);
            p[2] = f2tf32(aReg[s].z); p[3] = f2tf32(aReg[s].w);
            int kk = j >> 5, n4 = (j & 31) << 2;
            uint32_t* q = &Bs[buf][kk * BSTR + n4];
            q[0] = f2tf32(bReg[s].x); q[1] = f2tf32(bReg[s].y);
            q[2] = f2tf32(bReg[s].z); q[3] = f2tf32(bReg[s].w);
        }
    };

    float acc[2][8][4] = {};

    auto compute = [&](int buf) {
        #pragma unroll
        for (int k8 = 0; k8 < 2; k8++) {
            uint32_t a[2][4], b[8][2];
            #pragma unroll
            for (int mi = 0; mi < 2; mi++) {
                int r = wm * 32 + mi * 16 + (lane >> 2);
                int c = k8 * 8 + (lane & 3);
                a[mi][0] = As[buf][r * ASTR + c];
                a[mi][1] = As[buf][(r + 8) * ASTR + c];
                a[mi][2] = As[buf][r * ASTR + c + 4];
                a[mi][3] = As[buf][(r + 8) * ASTR + c + 4];
            }
            #pragma unroll
            for (int ni = 0; ni < 8; ni++) {
                int kk = k8 * 8 + (lane & 3);
                int n = wn * 64 + ni * 8 + (lane >> 2);
                b[ni][0] = Bs[buf][kk * BSTR + n];
                b[ni][1] = Bs[buf][(kk + 4) * BSTR + n];
            }
            #pragma unroll
            for (int mi = 0; mi < 2; mi++)
                #pragma unroll
                for (int ni = 0; ni < 8; ni++)
                    mma_tf32(acc[mi][ni], a[mi], b[ni]);
        }
    };

    int nk = K / TBK;
    ldg(0);
    sts(0);
    __syncthreads();
    for (int kt = 0; kt < nk; kt++) {
        if (kt + 1 < nk) ldg((kt + 1) * TBK);
        compute(kt & 1);
        if (kt + 1 < nk) sts((kt + 1) & 1);
        __syncthreads();
    }

    #pragma unroll
    for (int mi = 0; mi < 2; mi++) {
        int r0 = mBase + wm * 32 + mi * 16 + (lane >> 2);
        #pragma unroll
        for (int ni = 0; ni < 8; ni++) {
            int col = nBase + wn * 64 + ni * 8 + (lane & 3) * 2;
            if (r0 < M)
                *(float2*)(Cp + (size_t)r0 * N + col) =
                    make_float2(acc[mi][ni][0], acc[mi][ni][1]);
            if (r0 + 8 < M)
                *(float2*)(Cp + (size_t)(r0 + 8) * N + col) =
                    make_float2(acc[mi][ni][2], acc[mi][ni][3]);
        }
    }
}

// ---------------------------------------------------------------------------
// Depthwise 3x3, pad 1 (cross-correlation). 4 outputs/thread, float4 I/O.
__global__ void dwconv_kernel(const float* __restrict__ w) {
    size_t t = (size_t)blockIdx.x * blockDim.x + threadIdx.x;
    int x4 = (int)(t & 63) * 4;
    int y  = (int)((t >> 6) & (HH - 1));
    size_t plane = t >> 14;
    if (plane >= (size_t)NB * C3) return;
    int ch = (int)(plane % C3);
    const float* in = g_qkv1 + plane * HWN;
    const float* wp = w + ch * 9;
    float acc0 = 0.f, acc1 = 0.f, acc2 = 0.f, acc3 = 0.f;
    #pragma unroll
    for (int dy = 0; dy < 3; dy++) {
        int yy = y + dy - 1;
        if (yy < 0 || yy >= HH) continue;
        const float* rp = in + yy * WW + x4;
        float4 c = *(const float4*)rp;
        float left  = (x4 > 0)      ? rp[-1] : 0.f;
        float right = (x4 + 4 < WW) ? rp[4]  : 0.f;
        float w0 = wp[dy * 3], w1 = wp[dy * 3 + 1], w2 = wp[dy * 3 + 2];
        acc0 += w0 * left + w1 * c.x + w2 * c.y;
        acc1 += w0 * c.x  + w1 * c.y + w2 * c.z;
        acc2 += w0 * c.y  + w1 * c.z + w2 * c.w;
        acc3 += w0 * c.z  + w1 * c.w + w2 * right;
    }
    *(float4*)(g_qkv2 + plane * HWN + y * WW + x4) =
        make_float4(acc0, acc1, acc2, acc3);
}

// ---------------------------------------------------------------------------
// Gram = q @ k^T per (b,h): [48,48], K split across 64 blocks (atomicAdd).
#define GK 64
#define GSPAN 1024
__global__ void gram_kernel() {
    int bh = blockIdx.y;
    int b = bh >> 2, h = bh & 3;
    const float* qb = g_qkv2 + ((size_t)b * C3 + h * HD) * HWN;
    const float* kb = g_qkv2 + ((size_t)b * C3 + CC + h * HD) * HWN;

    __shared__ float qs[GK][HD + 1];
    __shared__ float ks[GK][HD + 1];

    int tid = threadIdx.x;
    int tx = tid & 15, ty = tid >> 4;
    float acc[3][3] = {};

    int n0 = blockIdx.x * GSPAN;
    for (int nc = 0; nc < GSPAN; nc += GK) {
        int nb = n0 + nc;
        for (int i = tid; i < HD * GK; i += 256) {
            int kk = i & (GK - 1);
            int c  = i >> 6;
            qs[kk][c] = qb[(size_t)c * HWN + nb + kk];
            ks[kk][c] = kb[(size_t)c * HWN + nb + kk];
        }
        __syncthreads();
        #pragma unroll 8
        for (int kk = 0; kk < GK; kk++) {
            float qv[3], kv[3];
            #pragma unroll
            for (int i = 0; i < 3; i++) qv[i] = qs[kk][ty + 16 * i];
            #pragma unroll
            for (int j = 0; j < 3; j++) kv[j] = ks[kk][tx + 16 * j];
            #pragma unroll
            for (int i = 0; i < 3; i++)
                #pragma unroll
                for (int j = 0; j < 3; j++)
                    acc[i][j] += qv[i] * kv[j];
        }
        __syncthreads();
    }
    #pragma unroll
    for (int i = 0; i < 3; i++)
        #pragma unroll
        for (int j = 0; j < 3; j++)
            atomicAdd(&g_gram[((size_t)bh * HD + ty + 16 * i) * HD + tx + 16 * j],
                      acc[i][j]);
}

// ---------------------------------------------------------------------------
__global__ void rownorm_kernel() {
    int r  = blockIdx.x;
    int b  = r / (2 * CC);
    int ch = r % (2 * CC);
    const float4* p = (const float4*)(g_qkv2 + ((size_t)b * C3 + ch) * HWN);
    float ss = 0.f;
    for (int i = threadIdx.x; i < HWN / 4; i += 256) {
        float4 v = p[i];
        ss += v.x * v.x + v.y * v.y + v.z * v.z + v.w * v.w;
    }
    __shared__ float red[256];
    red[threadIdx.x] = ss;
    __syncthreads();
    for (int s = 128; s > 0; s >>= 1) {
        if (threadIdx.x < s) red[threadIdx.x] += red[threadIdx.x + s];
        __syncthreads();
    }
    if (threadIdx.x == 0) g_norms[r] = fmaxf(sqrtf(red[0]), 1e-12f);
}

// ---------------------------------------------------------------------------
__global__ void attn_kernel(const float* __restrict__ temp) {
    int r = blockIdx.x * blockDim.x + threadIdx.x;
    if (r >= NB * NHD * HD) return;
    int b = r / (NHD * HD);
    int h = (r / HD) % NHD;
    int c = r % HD;
    float nq = g_norms[b * 2 * CC + h * HD + c];
    const float* gr = g_gram + (size_t)((b * NHD + h) * HD + c) * HD;
    float t = temp[h];
    float a[HD];
    float mx = -1e30f;
    for (int d = 0; d < HD; d++) {
        float nk = g_norms[b * 2 * CC + CC + h * HD + d];
        float v = gr[d] / (nq * nk) * t;
        a[d] = v;
        mx = fmaxf(mx, v);
    }
    float sum = 0.f;
    for (int d = 0; d < HD; d++) { a[d] = expf(a[d] - mx); sum += a[d]; }
    float inv = 1.f / sum;
    float* o = g_attn + (size_t)((b * NHD + h) * HD + c) * HD;
    for (int d = 0; d < HD; d++) o[d] = a[d] * inv;
}

// ---------------------------------------------------------------------------
__global__ void av_kernel() {
    int bh = blockIdx.y;
    int b = bh >> 2, h = bh & 3;
    __shared__ float sa[HD * HD];
    for (int i = threadIdx.x; i < HD * HD; i += 256)
        sa[i] = g_attn[(size_t)bh * HD * HD + i];
    __syncthreads();
    int n = blockIdx.x * 256 + threadIdx.x;
    const float* vb = g_qkv2 + ((size_t)b * C3 + 2 * CC + h * HD) * HWN + n;
    float*       ob = g_attout + ((size_t)b * CC + h * HD) * HWN + n;
    float acc[HD];
    #pragma unroll
    for (int c = 0; c < HD; c++) acc[c] = 0.f;
    #pragma unroll 4
    for (int d = 0; d < HD; d++) {
        float v = vb[(size_t)d * HWN];
        #pragma unroll
        for (int c = 0; c < HD; c++) acc[c] += sa[c * HD + d] * v;
    }
    #pragma unroll
    for (int c = 0; c < HD; c++) ob[(size_t)c * HWN] = acc[c];
}

// ---------------------------------------------------------------------------
extern "C" void kernel_launch(void* const* d_in, const int* in_sizes, int n_in,
                              void* d_out, int out_size) {
    const float* x      = (const float*)d_in[0];
    const float* qkv_w  = (const float*)d_in[1];
    const float* dw_w   = (const float*)d_in[2];
    const float* proj_w = (const float*)d_in[3];
    const float* temp   = (const float*)d_in[4];
    float* out = (float*)d_out;

    float *qkv1, *attout;
    cudaGetSymbolAddress((void**)&qkv1,   g_qkv1);
    cudaGetSymbolAddress((void**)&attout, g_attout);

    // launch 1
    zero_kernel<<<(NB * NHD * HD * HD + 255) / 256, 256>>>();

    // launch 2: qkv = qkv_w @ x
    tf32_gemm<<<dim3(HWN / TBN, (C3 + TBM - 1) / TBM, NB), 256>>>(
        qkv_w, x, qkv1, C3, HWN, CC, (size_t)CC * HWN, (size_t)C3 * HWN);

    // launch 3: dwconv
    dwconv_kernel<<<(int)(((size_t)NB * C3 * HWN) / 4 / 256), 256>>>(dw_w);

    // launch 4: gram (ncu capture slot)
    gram_kernel<<<dim3(HWN / GSPAN, NB * NHD), 256>>>();

    rownorm_kernel<<<NB * 2 * CC, 256>>>();

    attn_kernel<<<2, 192>>>(temp);

    av_kernel<<<dim3(HWN / 256, NB * NHD), 256>>>();

    // final = proj_w @ attout
    tf32_gemm<<<dim3(HWN / TBN, (CC + TBM - 1) / TBM, NB), 256>>>(
        proj_w, attout, out, CC, HWN, CC, (size_t)CC * HWN, (size_t)CC * HWN);
}

// round 8
// speedup vs baseline: 1.8807x; 1.1822x over previous
#include <cuda_runtime.h>
#include <math.h>
#include <stdint.h>

#define CC   192
#define C3   576
#define NB   2
#define NHD  4
#define HD   48
#define HH   256
#define WW   256
#define HWN  65536

// Scratch (device globals — allocation-free rule)
__device__ float g_qkv1[(size_t)NB * C3 * HWN];     // after 1x1 qkv conv
__device__ float g_qkv2[(size_t)NB * C3 * HWN];     // after depthwise 3x3
__device__ float g_attout[(size_t)NB * CC * HWN];   // attention output (pre-proj)
__device__ float g_gram[NB * NHD * HD * HD];        // raw q.k^T accumulators
__device__ float g_attn[NB * NHD * HD * HD];        // softmaxed attention
__device__ float g_norms[NB * 2 * CC];              // L2 norms q, then k

// ---------------------------------------------------------------------------
__global__ void zero_kernel() {
    int i = blockIdx.x * blockDim.x + threadIdx.x;
    if (i < NB * NHD * HD * HD) g_gram[i] = 0.f;
}

// ---------------------------------------------------------------------------
__device__ __forceinline__ uint32_t f2tf32(float f) {
    uint32_t u;
    asm("cvt.rna.tf32.f32 %0, %1;" : "=r"(u) : "f"(f));
    return u;
}

__device__ __forceinline__ void mma_tf32(float* c, const uint32_t* a, const uint32_t* b) {
    asm volatile(
        "mma.sync.aligned.m16n8k8.row.col.f32.tf32.tf32.f32 "
        "{%0,%1,%2,%3}, {%4,%5,%6,%7}, {%8,%9}, {%0,%1,%2,%3};"
        : "+f"(c[0]), "+f"(c[1]), "+f"(c[2]), "+f"(c[3])
        : "r"(a[0]), "r"(a[1]), "r"(a[2]), "r"(a[3]), "r"(b[0]), "r"(b[1]));
}

// ---------------------------------------------------------------------------
// TF32 tensor-core GEMM (proven config): block 128x128, BK=16, 8 warps,
// warp tile 32x64, occ 2.
#define TBM 128
#define TBN 128
#define TBK 16
#define ASTR 20
#define BSTR 136

__global__ void __launch_bounds__(256, 2)
tf32_gemm(const float* __restrict__ A, const float* __restrict__ B,
          float* __restrict__ C, int M, int N, int K,
          size_t strideB, size_t strideC) {
    const float* Bp = B + (size_t)blockIdx.z * strideB;
    float*       Cp = C + (size_t)blockIdx.z * strideC;

    __shared__ uint32_t As[2][TBM * ASTR];
    __shared__ uint32_t Bs[2][TBK * BSTR];

    int tid = threadIdx.x, lane = tid & 31, warp = tid >> 5;
    int wm = warp >> 1, wn = warp & 1;
    int mBase = blockIdx.y * TBM, nBase = blockIdx.x * TBN;

    float4 aReg[2], bReg[2];

    auto ldg = [&](int k0) {
        #pragma unroll
        for (int s = 0; s < 2; s++) {
            int j = tid + 256 * s;
            int row = j >> 2, kc = (j & 3) << 2;
            int gr = mBase + row;
            if (gr < M) aReg[s] = *(const float4*)(A + (size_t)gr * K + k0 + kc);
            else        aReg[s] = make_float4(0.f, 0.f, 0.f, 0.f);
            int kk = j >> 5, n4 = (j & 31) << 2;
            bReg[s] = *(const float4*)(Bp + (size_t)(k0 + kk) * N + nBase + n4);
        }
    };
    auto sts = [&](int buf) {
        #pragma unroll
        for (int s = 0; s < 2; s++) {
            int j = tid + 256 * s;
            int row = j >> 2, kc = (j & 3) << 2;
            uint32_t* p = &As[buf][row * ASTR + kc];
            p[0] = f2tf32(aReg[s].x); p[1] = f2tf32(aReg[s].y);
            p[2] = f2tf32(aReg[s].z); p[3] = f2tf32(aReg[s].w);
            int kk = j >> 5, n4 = (j & 31) << 2;
            uint32_t* q = &Bs[buf][kk * BSTR + n4];
            q[0] = f2tf32(bReg[s].x); q[1] = f2tf32(bReg[s].y);
            q[2] = f2tf32(bReg[s].z); q[3] = f2tf32(bReg[s].w);
        }
    };

    float acc[2][8][4] = {};

    auto compute = [&](int buf) {
        #pragma unroll
        for (int k8 = 0; k8 < 2; k8++) {
            uint32_t a[2][4], b[8][2];
            #pragma unroll
            for (int mi = 0; mi < 2; mi++) {
                int r = wm * 32 + mi * 16 + (lane >> 2);
                int c = k8 * 8 + (lane & 3);
                a[mi][0] = As[buf][r * ASTR + c];
                a[mi][1] = As[buf][(r + 8) * ASTR + c];
                a[mi][2] = As[buf][r * ASTR + c + 4];
                a[mi][3] = As[buf][(r + 8) * ASTR + c + 4];
            }
            #pragma unroll
            for (int ni = 0; ni < 8; ni++) {
                int kk = k8 * 8 + (lane & 3);
                int n = wn * 64 + ni * 8 + (lane >> 2);
                b[ni][0] = Bs[buf][kk * BSTR + n];
                b[ni][1] = Bs[buf][(kk + 4) * BSTR + n];
            }
            #pragma unroll
            for (int mi = 0; mi < 2; mi++)
                #pragma unroll
                for (int ni = 0; ni < 8; ni++)
                    mma_tf32(acc[mi][ni], a[mi], b[ni]);
        }
    };

    int nk = K / TBK;
    ldg(0);
    sts(0);
    __syncthreads();
    for (int kt = 0; kt < nk; kt++) {
        if (kt + 1 < nk) ldg((kt + 1) * TBK);
        compute(kt & 1);
        if (kt + 1 < nk) sts((kt + 1) & 1);
        __syncthreads();
    }

    #pragma unroll
    for (int mi = 0; mi < 2; mi++) {
        int r0 = mBase + wm * 32 + mi * 16 + (lane >> 2);
        #pragma unroll
        for (int ni = 0; ni < 8; ni++) {
            int col = nBase + wn * 64 + ni * 8 + (lane & 3) * 2;
            if (r0 < M)
                *(float2*)(Cp + (size_t)r0 * N + col) =
                    make_float2(acc[mi][ni][0], acc[mi][ni][1]);
            if (r0 + 8 < M)
                *(float2*)(Cp + (size_t)(r0 + 8) * N + col) =
                    make_float2(acc[mi][ni][2], acc[mi][ni][3]);
        }
    }
}

// ---------------------------------------------------------------------------
// Depthwise 3x3, pad 1 (cross-correlation). 4x4 output strip per thread:
// 6 input rows loaded once, reused across 4 output rows.
__global__ void dwconv_kernel(const float* __restrict__ w) {
    size_t t = (size_t)blockIdx.x * blockDim.x + threadIdx.x;
    int x4 = (int)(t & 63) * 4;          // 64 col-groups of 4
    int y4 = (int)((t >> 6) & 63) * 4;   // 64 row-groups of 4
    size_t plane = t >> 12;
    if (plane >= (size_t)NB * C3) return;
    int ch = (int)(plane % C3);
    const float* in = g_qkv1 + plane * HWN;
    const float* wp = w + ch * 9;
    float w00 = wp[0], w01 = wp[1], w02 = wp[2];
    float w10 = wp[3], w11 = wp[4], w12 = wp[5];
    float w20 = wp[6], w21 = wp[7], w22 = wp[8];

    float4 rC[6];
    float  rL[6], rR[6];
    #pragma unroll
    for (int j = 0; j < 6; j++) {
        int yy = y4 - 1 + j;
        if (yy < 0 || yy >= HH) {
            rC[j] = make_float4(0.f, 0.f, 0.f, 0.f);
            rL[j] = 0.f; rR[j] = 0.f;
        } else {
            const float* rp = in + yy * WW + x4;
            rC[j] = *(const float4*)rp;
            rL[j] = (x4 > 0)      ? rp[-1] : 0.f;
            rR[j] = (x4 + 4 < WW) ? rp[4]  : 0.f;
        }
    }

    float* outp = g_qkv2 + plane * HWN + y4 * WW + x4;
    #pragma unroll
    for (int i = 0; i < 4; i++) {
        float4 o;
        o.x = w00 * rL[i]     + w01 * rC[i].x   + w02 * rC[i].y
            + w10 * rL[i + 1] + w11 * rC[i + 1].x + w12 * rC[i + 1].y
            + w20 * rL[i + 2] + w21 * rC[i + 2].x + w22 * rC[i + 2].y;
        o.y = w00 * rC[i].x   + w01 * rC[i].y   + w02 * rC[i].z
            + w10 * rC[i + 1].x + w11 * rC[i + 1].y + w12 * rC[i + 1].z
            + w20 * rC[i + 2].x + w21 * rC[i + 2].y + w22 * rC[i + 2].z;
        o.z = w00 * rC[i].y   + w01 * rC[i].z   + w02 * rC[i].w
            + w10 * rC[i + 1].y + w11 * rC[i + 1].z + w12 * rC[i + 1].w
            + w20 * rC[i + 2].y + w21 * rC[i + 2].z + w22 * rC[i + 2].w;
        o.w = w00 * rC[i].z   + w01 * rC[i].w   + w02 * rR[i]
            + w10 * rC[i + 1].z + w11 * rC[i + 1].w + w12 * rR[i + 1]
            + w20 * rC[i + 2].z + w21 * rC[i + 2].w + w22 * rR[i + 2];
        *(float4*)(outp + i * WW) = o;
    }
}

// ---------------------------------------------------------------------------
// Tensor-core gram: D[qc][kc] = sum_s q[qc][s]*k[kc][s] per (b,h).
// 6 warps; warp owns one 8-col n-tile (no cross-warp reduction).
// 128 spatial splits; smem tiles pre-converted to tf32.
#define GSPL 128
#define GCH  64
#define QSTR 68
__global__ void __launch_bounds__(192)
gram_kernel() {
    int bh = blockIdx.y;
    int b = bh >> 2, h = bh & 3;
    const float* qb = g_qkv2 + ((size_t)b * C3 + h * HD) * HWN;
    const float* kb = g_qkv2 + ((size_t)b * C3 + CC + h * HD) * HWN;

    __shared__ uint32_t qs[HD * QSTR];
    __shared__ uint32_t ks[HD * QSTR];

    int tid = threadIdx.x, lane = tid & 31, warp = tid >> 5;  // 6 warps
    int n0 = warp * 8;
    float acc[3][4] = {};

    int base = blockIdx.x * (HWN / GSPL);   // 512-wide spatial span
    for (int cs = 0; cs < HWN / GSPL; cs += GCH) {
        int s0 = base + cs;
        for (int i = tid; i < HD * GCH / 4; i += 192) {
            int c = i >> 4, s4 = (i & 15) << 2;
            float4 qv = *(const float4*)(qb + (size_t)c * HWN + s0 + s4);
            float4 kv = *(const float4*)(kb + (size_t)c * HWN + s0 + s4);
            uint32_t* qp = &qs[c * QSTR + s4];
            qp[0] = f2tf32(qv.x); qp[1] = f2tf32(qv.y);
            qp[2] = f2tf32(qv.z); qp[3] = f2tf32(qv.w);
            uint32_t* kp = &ks[c * QSTR + s4];
            kp[0] = f2tf32(kv.x); kp[1] = f2tf32(kv.y);
            kp[2] = f2tf32(kv.z); kp[3] = f2tf32(kv.w);
        }
        __syncthreads();
        #pragma unroll
        for (int k8 = 0; k8 < GCH / 8; k8++) {
            int k0 = k8 * 8 + (lane & 3);
            uint32_t bf[2];
            int brow = n0 + (lane >> 2);
            bf[0] = ks[brow * QSTR + k0];
            bf[1] = ks[brow * QSTR + k0 + 4];
            #pragma unroll
            for (int mi = 0; mi < 3; mi++) {
                int ar = mi * 16 + (lane >> 2);
                uint32_t af[4];
                af[0] = qs[ar * QSTR + k0];
                af[1] = qs[(ar + 8) * QSTR + k0];
                af[2] = qs[ar * QSTR + k0 + 4];
                af[3] = qs[(ar + 8) * QSTR + k0 + 4];
                mma_tf32(acc[mi], af, bf);
            }
        }
        __syncthreads();
    }

    float* gp = g_gram + (size_t)bh * HD * HD;
    int col = n0 + (lane & 3) * 2;
    #pragma unroll
    for (int mi = 0; mi < 3; mi++) {
        int r = mi * 16 + (lane >> 2);
        atomicAdd(&gp[r * HD + col],           acc[mi][0]);
        atomicAdd(&gp[r * HD + col + 1],       acc[mi][1]);
        atomicAdd(&gp[(r + 8) * HD + col],     acc[mi][2]);
        atomicAdd(&gp[(r + 8) * HD + col + 1], acc[mi][3]);
    }
}

// ---------------------------------------------------------------------------
__global__ void rownorm_kernel() {
    int r  = blockIdx.x;
    int b  = r / (2 * CC);
    int ch = r % (2 * CC);
    const float4* p = (const float4*)(g_qkv2 + ((size_t)b * C3 + ch) * HWN);
    float ss = 0.f;
    for (int i = threadIdx.x; i < HWN / 4; i += 256) {
        float4 v = p[i];
        ss += v.x * v.x + v.y * v.y + v.z * v.z + v.w * v.w;
    }
    __shared__ float red[256];
    red[threadIdx.x] = ss;
    __syncthreads();
    for (int s = 128; s > 0; s >>= 1) {
        if (threadIdx.x < s) red[threadIdx.x] += red[threadIdx.x + s];
        __syncthreads();
    }
    if (threadIdx.x == 0) g_norms[r] = fmaxf(sqrtf(red[0]), 1e-12f);
}

// ---------------------------------------------------------------------------
__global__ void attn_kernel(const float* __restrict__ temp) {
    int r = blockIdx.x * blockDim.x + threadIdx.x;
    if (r >= NB * NHD * HD) return;
    int b = r / (NHD * HD);
    int h = (r / HD) % NHD;
    int c = r % HD;
    float nq = g_norms[b * 2 * CC + h * HD + c];
    const float* gr = g_gram + (size_t)((b * NHD + h) * HD + c) * HD;
    float t = temp[h];
    float a[HD];
    float mx = -1e30f;
    for (int d = 0; d < HD; d++) {
        float nk = g_norms[b * 2 * CC + CC + h * HD + d];
        float v = gr[d] / (nq * nk) * t;
        a[d] = v;
        mx = fmaxf(mx, v);
    }
    float sum = 0.f;
    for (int d = 0; d < HD; d++) { a[d] = expf(a[d] - mx); sum += a[d]; }
    float inv = 1.f / sum;
    float* o = g_attn + (size_t)((b * NHD + h) * HD + c) * HD;
    for (int d = 0; d < HD; d++) o[d] = a[d] * inv;
}

// ---------------------------------------------------------------------------
__global__ void av_kernel() {
    int bh = blockIdx.y;
    int b = bh >> 2, h = bh & 3;
    __shared__ float sa[HD * HD];
    for (int i = threadIdx.x; i < HD * HD; i += 256)
        sa[i] = g_attn[(size_t)bh * HD * HD + i];
    __syncthreads();
    int n = blockIdx.x * 256 + threadIdx.x;
    const float* vb = g_qkv2 + ((size_t)b * C3 + 2 * CC + h * HD) * HWN + n;
    float*       ob = g_attout + ((size_t)b * CC + h * HD) * HWN + n;
    float acc[HD];
    #pragma unroll
    for (int c = 0; c < HD; c++) acc[c] = 0.f;
    #pragma unroll 4
    for (int d = 0; d < HD; d++) {
        float v = vb[(size_t)d * HWN];
        #pragma unroll
        for (int c = 0; c < HD; c++) acc[c] += sa[c * HD + d] * v;
    }
    #pragma unroll
    for (int c = 0; c < HD; c++) ob[(size_t)c * HWN] = acc[c];
}

// ---------------------------------------------------------------------------
extern "C" void kernel_launch(void* const* d_in, const int* in_sizes, int n_in,
                              void* d_out, int out_size) {
    const float* x      = (const float*)d_in[0];
    const float* qkv_w  = (const float*)d_in[1];
    const float* dw_w   = (const float*)d_in[2];
    const float* proj_w = (const float*)d_in[3];
    const float* temp   = (const float*)d_in[4];
    float* out = (float*)d_out;

    float *qkv1, *attout;
    cudaGetSymbolAddress((void**)&qkv1,   g_qkv1);
    cudaGetSymbolAddress((void**)&attout, g_attout);

    // launch 1
    zero_kernel<<<(NB * NHD * HD * HD + 255) / 256, 256>>>();

    // launch 2: qkv = qkv_w @ x
    tf32_gemm<<<dim3(HWN / TBN, (C3 + TBM - 1) / TBM, NB), 256>>>(
        qkv_w, x, qkv1, C3, HWN, CC, (size_t)CC * HWN, (size_t)C3 * HWN);

    // launch 3: dwconv (4x4 strips)
    dwconv_kernel<<<(int)(((size_t)NB * C3 * HWN) / 16 / 256), 256>>>(dw_w);

    // launch 4: gram (tensor cores) — ncu capture slot
    gram_kernel<<<dim3(GSPL, NB * NHD), 192>>>();

    rownorm_kernel<<<NB * 2 * CC, 256>>>();

    attn_kernel<<<2, 192>>>(temp);

    av_kernel<<<dim3(HWN / 256, NB * NHD), 256>>>();

    // final = proj_w @ attout
    tf32_gemm<<<dim3(HWN / TBN, (CC + TBM - 1) / TBM, NB), 256>>>(
        proj_w, attout, out, CC, HWN, CC, (size_t)CC * HWN, (size_t)CC * HWN);
}

// round 9
// speedup vs baseline: 2.5273x; 1.3438x over previous
#include <cuda_runtime.h>
#include <math.h>
#include <stdint.h>

#define CC   192
#define C3   576
#define NB   2
#define NHD  4
#define HD   48
#define HH   256
#define WW   256
#define HWN  65536

// Scratch (device globals — allocation-free rule)
__device__ float g_qkv1[(size_t)NB * C3 * HWN];     // after 1x1 qkv conv
__device__ float g_qkv2[(size_t)NB * C3 * HWN];     // after depthwise 3x3
__device__ float g_gram[NB * NHD * HD * HD];        // raw q.k^T accumulators
__device__ float g_attn[NB * NHD * HD * HD];        // softmaxed attention
__device__ float g_norms[NB * 2 * CC];              // L2 norms q, then k
__device__ float g_m2[NB * CC * CC];                // proj_w @ blockdiag(attn)

// ---------------------------------------------------------------------------
__global__ void zero_kernel() {
    int i = blockIdx.x * blockDim.x + threadIdx.x;
    if (i < NB * NHD * HD * HD) g_gram[i] = 0.f;
}
__global__ void dummy_kernel() {}

// ---------------------------------------------------------------------------
__device__ __forceinline__ uint32_t f2tf32(float f) {
    uint32_t u;
    asm("cvt.rna.tf32.f32 %0, %1;" : "=r"(u) : "f"(f));
    return u;
}

__device__ __forceinline__ void mma_tf32(float* c, const uint32_t* a, const uint32_t* b) {
    asm volatile(
        "mma.sync.aligned.m16n8k8.row.col.f32.tf32.tf32.f32 "
        "{%0,%1,%2,%3}, {%4,%5,%6,%7}, {%8,%9}, {%0,%1,%2,%3};"
        : "+f"(c[0]), "+f"(c[1]), "+f"(c[2]), "+f"(c[3])
        : "r"(a[0]), "r"(a[1]), "r"(a[2]), "r"(a[3]), "r"(b[0]), "r"(b[1]));
}

// ---------------------------------------------------------------------------
// TF32 tensor-core GEMM (proven config): block 128x128, BK=16, 8 warps,
// warp tile 32x64, occ 2. A may be batched via strideA (0 = shared).
#define TBM 128
#define TBN 128
#define TBK 16
#define ASTR 20
#define BSTR 136

__global__ void __launch_bounds__(256, 2)
tf32_gemm(const float* __restrict__ A, const float* __restrict__ B,
          float* __restrict__ C, int M, int N, int K,
          size_t strideA, size_t strideB, size_t strideC) {
    const float* Ap = A + (size_t)blockIdx.z * strideA;
    const float* Bp = B + (size_t)blockIdx.z * strideB;
    float*       Cp = C + (size_t)blockIdx.z * strideC;

    __shared__ uint32_t As[2][TBM * ASTR];
    __shared__ uint32_t Bs[2][TBK * BSTR];

    int tid = threadIdx.x, lane = tid & 31, warp = tid >> 5;
    int wm = warp >> 1, wn = warp & 1;
    int mBase = blockIdx.y * TBM, nBase = blockIdx.x * TBN;

    float4 aReg[2], bReg[2];

    auto ldg = [&](int k0) {
        #pragma unroll
        for (int s = 0; s < 2; s++) {
            int j = tid + 256 * s;
            int row = j >> 2, kc = (j & 3) << 2;
            int gr = mBase + row;
            if (gr < M) aReg[s] = *(const float4*)(Ap + (size_t)gr * K + k0 + kc);
            else        aReg[s] = make_float4(0.f, 0.f, 0.f, 0.f);
            int kk = j >> 5, n4 = (j & 31) << 2;
            bReg[s] = *(const float4*)(Bp + (size_t)(k0 + kk) * N + nBase + n4);
        }
    };
    auto sts = [&](int buf) {
        #pragma unroll
        for (int s = 0; s < 2; s++) {
            int j = tid + 256 * s;
            int row = j >> 2, kc = (j & 3) << 2;
            uint32_t* p = &As[buf][row * ASTR + kc];
            p[0] = f2tf32(aReg[s].x); p[1] = f2tf32(aReg[s].y);
            p[2] = f2tf32(aReg[s].z); p[3] = f2tf32(aReg[s].w);
            int kk = j >> 5, n4 = (j & 31) << 2;
            uint32_t* q = &Bs[buf][kk * BSTR + n4];
            q[0] = f2tf32(bReg[s].x); q[1] = f2tf32(bReg[s].y);
            q[2] = f2tf32(bReg[s].z); q[3] = f2tf32(bReg[s].w);
        }
    };

    float acc[2][8][4] = {};

    auto compute = [&](int buf) {
        #pragma unroll
        for (int k8 = 0; k8 < 2; k8++) {
            uint32_t a[2][4], b[8][2];
            #pragma unroll
            for (int mi = 0; mi < 2; mi++) {
                int r = wm * 32 + mi * 16 + (lane >> 2);
                int c = k8 * 8 + (lane & 3);
                a[mi][0] = As[buf][r * ASTR + c];
                a[mi][1] = As[buf][(r + 8) * ASTR + c];
                a[mi][2] = As[buf][r * ASTR + c + 4];
                a[mi][3] = As[buf][(r + 8) * ASTR + c + 4];
            }
            #pragma unroll
            for (int ni = 0; ni < 8; ni++) {
                int kk = k8 * 8 + (lane & 3);
                int n = wn * 64 + ni * 8 + (lane >> 2);
                b[ni][0] = Bs[buf][kk * BSTR + n];
                b[ni][1] = Bs[buf][(kk + 4) * BSTR + n];
            }
            #pragma unroll
            for (int mi = 0; mi < 2; mi++)
                #pragma unroll
                for (int ni = 0; ni < 8; ni++)
                    mma_tf32(acc[mi][ni], a[mi], b[ni]);
        }
    };

    int nk = K / TBK;
    ldg(0);
    sts(0);
    __syncthreads();
    for (int kt = 0; kt < nk; kt++) {
        if (kt + 1 < nk) ldg((kt + 1) * TBK);
        compute(kt & 1);
        if (kt + 1 < nk) sts((kt + 1) & 1);
        __syncthreads();
    }

    #pragma unroll
    for (int mi = 0; mi < 2; mi++) {
        int r0 = mBase + wm * 32 + mi * 16 + (lane >> 2);
        #pragma unroll
        for (int ni = 0; ni < 8; ni++) {
            int col = nBase + wn * 64 + ni * 8 + (lane & 3) * 2;
            if (r0 < M)
                *(float2*)(Cp + (size_t)r0 * N + col) =
                    make_float2(acc[mi][ni][0], acc[mi][ni][1]);
            if (r0 + 8 < M)
                *(float2*)(Cp + (size_t)(r0 + 8) * N + col) =
                    make_float2(acc[mi][ni][2], acc[mi][ni][3]);
        }
    }
}

// ---------------------------------------------------------------------------
// Depthwise 3x3, pad 1 (cross-correlation). 4x4 output strip per thread.
__global__ void dwconv_kernel(const float* __restrict__ w) {
    size_t t = (size_t)blockIdx.x * blockDim.x + threadIdx.x;
    int x4 = (int)(t & 63) * 4;
    int y4 = (int)((t >> 6) & 63) * 4;
    size_t plane = t >> 12;
    if (plane >= (size_t)NB * C3) return;
    int ch = (int)(plane % C3);
    const float* in = g_qkv1 + plane * HWN;
    const float* wp = w + ch * 9;
    float w00 = wp[0], w01 = wp[1], w02 = wp[2];
    float w10 = wp[3], w11 = wp[4], w12 = wp[5];
    float w20 = wp[6], w21 = wp[7], w22 = wp[8];

    float4 rC[6];
    float  rL[6], rR[6];
    #pragma unroll
    for (int j = 0; j < 6; j++) {
        int yy = y4 - 1 + j;
        if (yy < 0 || yy >= HH) {
            rC[j] = make_float4(0.f, 0.f, 0.f, 0.f);
            rL[j] = 0.f; rR[j] = 0.f;
        } else {
            const float* rp = in + yy * WW + x4;
            rC[j] = *(const float4*)rp;
            rL[j] = (x4 > 0)      ? rp[-1] : 0.f;
            rR[j] = (x4 + 4 < WW) ? rp[4]  : 0.f;
        }
    }

    float* outp = g_qkv2 + plane * HWN + y4 * WW + x4;
    #pragma unroll
    for (int i = 0; i < 4; i++) {
        float4 o;
        o.x = w00 * rL[i]     + w01 * rC[i].x   + w02 * rC[i].y
            + w10 * rL[i + 1] + w11 * rC[i + 1].x + w12 * rC[i + 1].y
            + w20 * rL[i + 2] + w21 * rC[i + 2].x + w22 * rC[i + 2].y;
        o.y = w00 * rC[i].x   + w01 * rC[i].y   + w02 * rC[i].z
            + w10 * rC[i + 1].x + w11 * rC[i + 1].y + w12 * rC[i + 1].z
            + w20 * rC[i + 2].x + w21 * rC[i + 2].y + w22 * rC[i + 2].z;
        o.z = w00 * rC[i].y   + w01 * rC[i].z   + w02 * rC[i].w
            + w10 * rC[i + 1].y + w11 * rC[i + 1].z + w12 * rC[i + 1].w
            + w20 * rC[i + 2].y + w21 * rC[i + 2].z + w22 * rC[i + 2].w;
        o.w = w00 * rC[i].z   + w01 * rC[i].w   + w02 * rR[i]
            + w10 * rC[i + 1].z + w11 * rC[i + 1].w + w12 * rR[i + 1]
            + w20 * rC[i + 2].z + w21 * rC[i + 2].w + w22 * rR[i + 2];
        *(float4*)(outp + i * WW) = o;
    }
}

// ---------------------------------------------------------------------------
// Tensor-core gram: D[qc][kc] = sum_s q[qc][s]*k[kc][s] per (b,h).
#define GSPL 128
#define GCH  64
#define QSTR 68
__global__ void __launch_bounds__(192)
gram_kernel() {
    int bh = blockIdx.y;
    int b = bh >> 2, h = bh & 3;
    const float* qb = g_qkv2 + ((size_t)b * C3 + h * HD) * HWN;
    const float* kb = g_qkv2 + ((size_t)b * C3 + CC + h * HD) * HWN;

    __shared__ uint32_t qs[HD * QSTR];
    __shared__ uint32_t ks[HD * QSTR];

    int tid = threadIdx.x, lane = tid & 31, warp = tid >> 5;
    int n0 = warp * 8;
    float acc[3][4] = {};

    int base = blockIdx.x * (HWN / GSPL);
    for (int cs = 0; cs < HWN / GSPL; cs += GCH) {
        int s0 = base + cs;
        for (int i = tid; i < HD * GCH / 4; i += 192) {
            int c = i >> 4, s4 = (i & 15) << 2;
            float4 qv = *(const float4*)(qb + (size_t)c * HWN + s0 + s4);
            float4 kv = *(const float4*)(kb + (size_t)c * HWN + s0 + s4);
            uint32_t* qp = &qs[c * QSTR + s4];
            qp[0] = f2tf32(qv.x); qp[1] = f2tf32(qv.y);
            qp[2] = f2tf32(qv.z); qp[3] = f2tf32(qv.w);
            uint32_t* kp = &ks[c * QSTR + s4];
            kp[0] = f2tf32(kv.x); kp[1] = f2tf32(kv.y);
            kp[2] = f2tf32(kv.z); kp[3] = f2tf32(kv.w);
        }
        __syncthreads();
        #pragma unroll
        for (int k8 = 0; k8 < GCH / 8; k8++) {
            int k0 = k8 * 8 + (lane & 3);
            uint32_t bf[2];
            int brow = n0 + (lane >> 2);
            bf[0] = ks[brow * QSTR + k0];
            bf[1] = ks[brow * QSTR + k0 + 4];
            #pragma unroll
            for (int mi = 0; mi < 3; mi++) {
                int ar = mi * 16 + (lane >> 2);
                uint32_t af[4];
                af[0] = qs[ar * QSTR + k0];
                af[1] = qs[(ar + 8) * QSTR + k0];
                af[2] = qs[ar * QSTR + k0 + 4];
                af[3] = qs[(ar + 8) * QSTR + k0 + 4];
                mma_tf32(acc[mi], af, bf);
            }
        }
        __syncthreads();
    }

    float* gp = g_gram + (size_t)bh * HD * HD;
    int col = n0 + (lane & 3) * 2;
    #pragma unroll
    for (int mi = 0; mi < 3; mi++) {
        int r = mi * 16 + (lane >> 2);
        atomicAdd(&gp[r * HD + col],           acc[mi][0]);
        atomicAdd(&gp[r * HD + col + 1],       acc[mi][1]);
        atomicAdd(&gp[(r + 8) * HD + col],     acc[mi][2]);
        atomicAdd(&gp[(r + 8) * HD + col + 1], acc[mi][3]);
    }
}

// ---------------------------------------------------------------------------
__global__ void rownorm_kernel() {
    int r  = blockIdx.x;
    int b  = r / (2 * CC);
    int ch = r % (2 * CC);
    const float4* p = (const float4*)(g_qkv2 + ((size_t)b * C3 + ch) * HWN);
    float ss = 0.f;
    for (int i = threadIdx.x; i < HWN / 4; i += 256) {
        float4 v = p[i];
        ss += v.x * v.x + v.y * v.y + v.z * v.z + v.w * v.w;
    }
    __shared__ float red[256];
    red[threadIdx.x] = ss;
    __syncthreads();
    for (int s = 128; s > 0; s >>= 1) {
        if (threadIdx.x < s) red[threadIdx.x] += red[threadIdx.x + s];
        __syncthreads();
    }
    if (threadIdx.x == 0) g_norms[r] = fmaxf(sqrtf(red[0]), 1e-12f);
}

// ---------------------------------------------------------------------------
__global__ void attn_kernel(const float* __restrict__ temp) {
    int r = blockIdx.x * blockDim.x + threadIdx.x;
    if (r >= NB * NHD * HD) return;
    int b = r / (NHD * HD);
    int h = (r / HD) % NHD;
    int c = r % HD;
    float nq = g_norms[b * 2 * CC + h * HD + c];
    const float* gr = g_gram + (size_t)((b * NHD + h) * HD + c) * HD;
    float t = temp[h];
    float a[HD];
    float mx = -1e30f;
    for (int d = 0; d < HD; d++) {
        float nk = g_norms[b * 2 * CC + CC + h * HD + d];
        float v = gr[d] / (nq * nk) * t;
        a[d] = v;
        mx = fmaxf(mx, v);
    }
    float sum = 0.f;
    for (int d = 0; d < HD; d++) { a[d] = expf(a[d] - mx); sum += a[d]; }
    float inv = 1.f / sum;
    float* o = g_attn + (size_t)((b * NHD + h) * HD + c) * HD;
    for (int d = 0; d < HD; d++) o[d] = a[d] * inv;
}

// ---------------------------------------------------------------------------
// M2[b] = proj_w @ blockdiag(attn[b]) : M2[b][o][h*48+d] =
//   sum_c proj_w[o][h*48+c] * attn[b][h][c][d]
__global__ void m2_kernel(const float* __restrict__ P) {
    int idx = blockIdx.x * blockDim.x + threadIdx.x;
    if (idx >= NB * CC * CC) return;
    int b = idx / (CC * CC);
    int o = (idx / CC) % CC;
    int g = idx % CC;
    int h = g / HD, d = g % HD;
    const float* pr = P + (size_t)o * CC + h * HD;
    const float* at = g_attn + (size_t)((b * NHD + h) * HD) * HD + d;
    float s = 0.f;
    #pragma unroll
    for (int c = 0; c < HD; c++) s += pr[c] * at[c * HD];
    g_m2[idx] = s;
}

// ---------------------------------------------------------------------------
extern "C" void kernel_launch(void* const* d_in, const int* in_sizes, int n_in,
                              void* d_out, int out_size) {
    const float* x      = (const float*)d_in[0];
    const float* qkv_w  = (const float*)d_in[1];
    const float* dw_w   = (const float*)d_in[2];
    const float* proj_w = (const float*)d_in[3];
    const float* temp   = (const float*)d_in[4];
    float* out = (float*)d_out;

    float *qkv1, *qkv2, *m2;
    cudaGetSymbolAddress((void**)&qkv1, g_qkv1);
    cudaGetSymbolAddress((void**)&qkv2, g_qkv2);
    cudaGetSymbolAddress((void**)&m2,   g_m2);

    // launch 1
    zero_kernel<<<(NB * NHD * HD * HD + 255) / 256, 256>>>();

    // launch 2: qkv = qkv_w @ x
    tf32_gemm<<<dim3(HWN / TBN, (C3 + TBM - 1) / TBM, NB), 256>>>(
        qkv_w, x, qkv1, C3, HWN, CC,
        0, (size_t)CC * HWN, (size_t)C3 * HWN);

    // launch 3: slot shim (ncu captures launch #4)
    dummy_kernel<<<1, 1>>>();

    // launch 4: dwconv — profiled this round
    dwconv_kernel<<<(int)(((size_t)NB * C3 * HWN) / 16 / 256), 256>>>(dw_w);

    gram_kernel<<<dim3(GSPL, NB * NHD), 192>>>();

    rownorm_kernel<<<NB * 2 * CC, 256>>>();

    attn_kernel<<<2, 192>>>(temp);

    m2_kernel<<<(NB * CC * CC + 255) / 256, 256>>>(proj_w);

    // final: out[b] = M2[b] @ v[b]   (v = channels 2*CC.. of qkv2)
    tf32_gemm<<<dim3(HWN / TBN, (CC + TBM - 1) / TBM, NB), 256>>>(
        m2, qkv2 + (size_t)2 * CC * HWN, out, CC, HWN, CC,
        (size_t)CC * CC, (size_t)C3 * HWN, (size_t)CC * HWN);
}

// round 10
// speedup vs baseline: 2.7117x; 1.0729x over previous
#include <cuda_runtime.h>
#include <math.h>
#include <stdint.h>

#define CC   192
#define C3   576
#define NB   2
#define NHD  4
#define HD   48
#define HH   256
#define WW   256
#define HWN  65536

// Scratch (device globals — allocation-free rule)
__device__ float g_qkv1[(size_t)NB * C3 * HWN];     // after 1x1 qkv conv
__device__ float g_qkv2[(size_t)NB * C3 * HWN];     // after depthwise 3x3
__device__ float g_gram[NB * NHD * HD * HD];        // raw q.k^T accumulators
__device__ float g_attn[NB * NHD * HD * HD];        // softmaxed attention
__device__ float g_sumsq[NB * 2 * CC];              // sum-of-squares q, then k
__device__ float g_m2[NB * CC * CC];                // proj_w @ blockdiag(attn)

// ---------------------------------------------------------------------------
__global__ void zero_kernel() {
    int i = blockIdx.x * blockDim.x + threadIdx.x;
    if (i < NB * NHD * HD * HD) g_gram[i] = 0.f;
    if (i < NB * 2 * CC)        g_sumsq[i] = 0.f;
}

// ---------------------------------------------------------------------------
__device__ __forceinline__ uint32_t f2tf32(float f) {
    uint32_t u;
    asm("cvt.rna.tf32.f32 %0, %1;" : "=r"(u) : "f"(f));
    return u;
}

__device__ __forceinline__ void mma_tf32(float* c, const uint32_t* a, const uint32_t* b) {
    asm volatile(
        "mma.sync.aligned.m16n8k8.row.col.f32.tf32.tf32.f32 "
        "{%0,%1,%2,%3}, {%4,%5,%6,%7}, {%8,%9}, {%0,%1,%2,%3};"
        : "+f"(c[0]), "+f"(c[1]), "+f"(c[2]), "+f"(c[3])
        : "r"(a[0]), "r"(a[1]), "r"(a[2]), "r"(a[3]), "r"(b[0]), "r"(b[1]));
}

// ---------------------------------------------------------------------------
// TF32 tensor-core GEMM (proven config): block 128x128, BK=16, 8 warps,
// warp tile 32x64, occ 2. Compile-time K for full kt unroll.
#define TBM 128
#define TBN 128
#define TBK 16
#define ASTR 20
#define BSTR 136

template<int KC>
__global__ void __launch_bounds__(256, 2)
tf32_gemm(const float* __restrict__ A, const float* __restrict__ B,
          float* __restrict__ C, int M, int N,
          size_t strideA, size_t strideB, size_t strideC) {
    const float* Ap = A + (size_t)blockIdx.z * strideA;
    const float* Bp = B + (size_t)blockIdx.z * strideB;
    float*       Cp = C + (size_t)blockIdx.z * strideC;

    __shared__ uint32_t As[2][TBM * ASTR];
    __shared__ uint32_t Bs[2][TBK * BSTR];

    int tid = threadIdx.x, lane = tid & 31, warp = tid >> 5;
    int wm = warp >> 1, wn = warp & 1;
    int mBase = blockIdx.y * TBM, nBase = blockIdx.x * TBN;

    float4 aReg[2], bReg[2];

    auto ldg = [&](int k0) {
        #pragma unroll
        for (int s = 0; s < 2; s++) {
            int j = tid + 256 * s;
            int row = j >> 2, kc = (j & 3) << 2;
            int gr = mBase + row;
            if (gr < M) aReg[s] = *(const float4*)(Ap + (size_t)gr * KC + k0 + kc);
            else        aReg[s] = make_float4(0.f, 0.f, 0.f, 0.f);
            int kk = j >> 5, n4 = (j & 31) << 2;
            bReg[s] = *(const float4*)(Bp + (size_t)(k0 + kk) * N + nBase + n4);
        }
    };
    auto sts = [&](int buf) {
        #pragma unroll
        for (int s = 0; s < 2; s++) {
            int j = tid + 256 * s;
            int row = j >> 2, kc = (j & 3) << 2;
            uint32_t* p = &As[buf][row * ASTR + kc];
            p[0] = f2tf32(aReg[s].x); p[1] = f2tf32(aReg[s].y);
            p[2] = f2tf32(aReg[s].z); p[3] = f2tf32(aReg[s].w);
            int kk = j >> 5, n4 = (j & 31) << 2;
            uint32_t* q = &Bs[buf][kk * BSTR + n4];
            q[0] = f2tf32(bReg[s].x); q[1] = f2tf32(bReg[s].y);
            q[2] = f2tf32(bReg[s].z); q[3] = f2tf32(bReg[s].w);
        }
    };

    float acc[2][8][4] = {};

    auto compute = [&](int buf) {
        #pragma unroll
        for (int k8 = 0; k8 < 2; k8++) {
            uint32_t a[2][4], b[8][2];
            #pragma unroll
            for (int mi = 0; mi < 2; mi++) {
                int r = wm * 32 + mi * 16 + (lane >> 2);
                int c = k8 * 8 + (lane & 3);
                a[mi][0] = As[buf][r * ASTR + c];
                a[mi][1] = As[buf][(r + 8) * ASTR + c];
                a[mi][2] = As[buf][r * ASTR + c + 4];
                a[mi][3] = As[buf][(r + 8) * ASTR + c + 4];
            }
            #pragma unroll
            for (int ni = 0; ni < 8; ni++) {
                int kk = k8 * 8 + (lane & 3);
                int n = wn * 64 + ni * 8 + (lane >> 2);
                b[ni][0] = Bs[buf][kk * BSTR + n];
                b[ni][1] = Bs[buf][(kk + 4) * BSTR + n];
            }
            #pragma unroll
            for (int mi = 0; mi < 2; mi++)
                #pragma unroll
                for (int ni = 0; ni < 8; ni++)
                    mma_tf32(acc[mi][ni], a[mi], b[ni]);
        }
    };

    constexpr int nk = KC / TBK;
    ldg(0);
    sts(0);
    __syncthreads();
    #pragma unroll
    for (int kt = 0; kt < nk; kt++) {
        if (kt + 1 < nk) ldg((kt + 1) * TBK);
        compute(kt & 1);
        if (kt + 1 < nk) sts((kt + 1) & 1);
        __syncthreads();
    }

    #pragma unroll
    for (int mi = 0; mi < 2; mi++) {
        int r0 = mBase + wm * 32 + mi * 16 + (lane >> 2);
        #pragma unroll
        for (int ni = 0; ni < 8; ni++) {
            int col = nBase + wn * 64 + ni * 8 + (lane & 3) * 2;
            if (r0 < M)
                *(float2*)(Cp + (size_t)r0 * N + col) =
                    make_float2(acc[mi][ni][0], acc[mi][ni][1]);
            if (r0 + 8 < M)
                *(float2*)(Cp + (size_t)(r0 + 8) * N + col) =
                    make_float2(acc[mi][ni][2], acc[mi][ni][3]);
        }
    }
}

// ---------------------------------------------------------------------------
// Depthwise 3x3, pad 1 (cross-correlation). 4x4 output strip per thread.
__global__ void dwconv_kernel(const float* __restrict__ w) {
    size_t t = (size_t)blockIdx.x * blockDim.x + threadIdx.x;
    int x4 = (int)(t & 63) * 4;
    int y4 = (int)((t >> 6) & 63) * 4;
    size_t plane = t >> 12;
    if (plane >= (size_t)NB * C3) return;
    int ch = (int)(plane % C3);
    const float* in = g_qkv1 + plane * HWN;
    const float* wp = w + ch * 9;
    float w00 = wp[0], w01 = wp[1], w02 = wp[2];
    float w10 = wp[3], w11 = wp[4], w12 = wp[5];
    float w20 = wp[6], w21 = wp[7], w22 = wp[8];

    float4 rC[6];
    float  rL[6], rR[6];
    #pragma unroll
    for (int j = 0; j < 6; j++) {
        int yy = y4 - 1 + j;
        if (yy < 0 || yy >= HH) {
            rC[j] = make_float4(0.f, 0.f, 0.f, 0.f);
            rL[j] = 0.f; rR[j] = 0.f;
        } else {
            const float* rp = in + yy * WW + x4;
            rC[j] = *(const float4*)rp;
            rL[j] = (x4 > 0)      ? rp[-1] : 0.f;
            rR[j] = (x4 + 4 < WW) ? rp[4]  : 0.f;
        }
    }

    float* outp = g_qkv2 + plane * HWN + y4 * WW + x4;
    #pragma unroll
    for (int i = 0; i < 4; i++) {
        float4 o;
        o.x = w00 * rL[i]     + w01 * rC[i].x   + w02 * rC[i].y
            + w10 * rL[i + 1] + w11 * rC[i + 1].x + w12 * rC[i + 1].y
            + w20 * rL[i + 2] + w21 * rC[i + 2].x + w22 * rC[i + 2].y;
        o.y = w00 * rC[i].x   + w01 * rC[i].y   + w02 * rC[i].z
            + w10 * rC[i + 1].x + w11 * rC[i + 1].y + w12 * rC[i + 1].z
            + w20 * rC[i + 2].x + w21 * rC[i + 2].y + w22 * rC[i + 2].z;
        o.z = w00 * rC[i].y   + w01 * rC[i].z   + w02 * rC[i].w
            + w10 * rC[i + 1].y + w11 * rC[i + 1].z + w12 * rC[i + 1].w
            + w20 * rC[i + 2].y + w21 * rC[i + 2].z + w22 * rC[i + 2].w;
        o.w = w00 * rC[i].z   + w01 * rC[i].w   + w02 * rR[i]
            + w10 * rC[i + 1].z + w11 * rC[i + 1].w + w12 * rR[i + 1]
            + w20 * rC[i + 2].z + w21 * rC[i + 2].w + w22 * rR[i + 2];
        *(float4*)(outp + i * WW) = o;
    }
}

// ---------------------------------------------------------------------------
// Tensor-core gram + fused per-channel sum-of-squares.
// Fill mapping: thread owns channel (tid>>2); quad (tid&3) covers 64 spatial
// contiguously per instruction (full-sector coalescing).
#define GSPL 128
#define GCH  64
#define QSTR 68
__global__ void __launch_bounds__(192)
gram_kernel() {
    int bh = blockIdx.y;
    int b = bh >> 2, h = bh & 3;
    const float* qb = g_qkv2 + ((size_t)b * C3 + h * HD) * HWN;
    const float* kb = g_qkv2 + ((size_t)b * C3 + CC + h * HD) * HWN;

    __shared__ uint32_t qs[HD * QSTR];
    __shared__ uint32_t ks[HD * QSTR];

    int tid = threadIdx.x, lane = tid & 31, warp = tid >> 5;
    int c_own = tid >> 2;      // 0..47
    int sg    = tid & 3;       // quad slot
    int n0 = warp * 8;
    float acc[3][4] = {};
    float ssq = 0.f, ssk = 0.f;

    int base = blockIdx.x * (HWN / GSPL);
    for (int cs = 0; cs < HWN / GSPL; cs += GCH) {
        int s0 = base + cs;
        const float* qrow = qb + (size_t)c_own * HWN + s0;
        const float* krow = kb + (size_t)c_own * HWN + s0;
        #pragma unroll
        for (int j = 0; j < 4; j++) {
            int s = j * 16 + sg * 4;
            float4 qv = *(const float4*)(qrow + s);
            float4 kv = *(const float4*)(krow + s);
            ssq += qv.x * qv.x + qv.y * qv.y + qv.z * qv.z + qv.w * qv.w;
            ssk += kv.x * kv.x + kv.y * kv.y + kv.z * kv.z + kv.w * kv.w;
            uint4 qt = make_uint4(f2tf32(qv.x), f2tf32(qv.y), f2tf32(qv.z), f2tf32(qv.w));
            uint4 kt = make_uint4(f2tf32(kv.x), f2tf32(kv.y), f2tf32(kv.z), f2tf32(kv.w));
            *(uint4*)&qs[c_own * QSTR + s] = qt;
            *(uint4*)&ks[c_own * QSTR + s] = kt;
        }
        __syncthreads();
        #pragma unroll
        for (int k8 = 0; k8 < GCH / 8; k8++) {
            int k0 = k8 * 8 + (lane & 3);
            uint32_t bf[2];
            int brow = n0 + (lane >> 2);
            bf[0] = ks[brow * QSTR + k0];
            bf[1] = ks[brow * QSTR + k0 + 4];
            #pragma unroll
            for (int mi = 0; mi < 3; mi++) {
                int ar = mi * 16 + (lane >> 2);
                uint32_t af[4];
                af[0] = qs[ar * QSTR + k0];
                af[1] = qs[(ar + 8) * QSTR + k0];
                af[2] = qs[ar * QSTR + k0 + 4];
                af[3] = qs[(ar + 8) * QSTR + k0 + 4];
                mma_tf32(acc[mi], af, bf);
            }
        }
        __syncthreads();
    }

    // gram output
    float* gp = g_gram + (size_t)bh * HD * HD;
    int col = n0 + (lane & 3) * 2;
    #pragma unroll
    for (int mi = 0; mi < 3; mi++) {
        int r = mi * 16 + (lane >> 2);
        atomicAdd(&gp[r * HD + col],           acc[mi][0]);
        atomicAdd(&gp[r * HD + col + 1],       acc[mi][1]);
        atomicAdd(&gp[(r + 8) * HD + col],     acc[mi][2]);
        atomicAdd(&gp[(r + 8) * HD + col + 1], acc[mi][3]);
    }

    // fused sum-of-squares: reduce across quad, one atomic per channel
    ssq += __shfl_xor_sync(0xffffffffu, ssq, 1);
    ssq += __shfl_xor_sync(0xffffffffu, ssq, 2);
    ssk += __shfl_xor_sync(0xffffffffu, ssk, 1);
    ssk += __shfl_xor_sync(0xffffffffu, ssk, 2);
    if (sg == 0) {
        atomicAdd(&g_sumsq[b * 2 * CC + h * HD + c_own], ssq);
        atomicAdd(&g_sumsq[b * 2 * CC + CC + h * HD + c_own], ssk);
    }
}

// ---------------------------------------------------------------------------
__global__ void attn_kernel(const float* __restrict__ temp) {
    int r = blockIdx.x * blockDim.x + threadIdx.x;
    if (r >= NB * NHD * HD) return;
    int b = r / (NHD * HD);
    int h = (r / HD) % NHD;
    int c = r % HD;
    float nq = fmaxf(sqrtf(g_sumsq[b * 2 * CC + h * HD + c]), 1e-12f);
    const float* gr = g_gram + (size_t)((b * NHD + h) * HD + c) * HD;
    float t = temp[h];
    float a[HD];
    float mx = -1e30f;
    for (int d = 0; d < HD; d++) {
        float nk = fmaxf(sqrtf(g_sumsq[b * 2 * CC + CC + h * HD + d]), 1e-12f);
        float v = gr[d] / (nq * nk) * t;
        a[d] = v;
        mx = fmaxf(mx, v);
    }
    float sum = 0.f;
    for (int d = 0; d < HD; d++) { a[d] = expf(a[d] - mx); sum += a[d]; }
    float inv = 1.f / sum;
    float* o = g_attn + (size_t)((b * NHD + h) * HD + c) * HD;
    for (int d = 0; d < HD; d++) o[d] = a[d] * inv;
}

// ---------------------------------------------------------------------------
// M2[b] = proj_w @ blockdiag(attn[b])
__global__ void m2_kernel(const float* __restrict__ P) {
    int idx = blockIdx.x * blockDim.x + threadIdx.x;
    if (idx >= NB * CC * CC) return;
    int b = idx / (CC * CC);
    int o = (idx / CC) % CC;
    int g = idx % CC;
    int h = g / HD, d = g % HD;
    const float* pr = P + (size_t)o * CC + h * HD;
    const float* at = g_attn + (size_t)((b * NHD + h) * HD) * HD + d;
    float s = 0.f;
    #pragma unroll
    for (int c = 0; c < HD; c++) s += pr[c] * at[c * HD];
    g_m2[idx] = s;
}

// ---------------------------------------------------------------------------
extern "C" void kernel_launch(void* const* d_in, const int* in_sizes, int n_in,
                              void* d_out, int out_size) {
    const float* x      = (const float*)d_in[0];
    const float* qkv_w  = (const float*)d_in[1];
    const float* dw_w   = (const float*)d_in[2];
    const float* proj_w = (const float*)d_in[3];
    const float* temp   = (const float*)d_in[4];
    float* out = (float*)d_out;

    float *qkv1, *qkv2, *m2;
    cudaGetSymbolAddress((void**)&qkv1, g_qkv1);
    cudaGetSymbolAddress((void**)&qkv2, g_qkv2);
    cudaGetSymbolAddress((void**)&m2,   g_m2);

    // launch 1
    zero_kernel<<<(NB * NHD * HD * HD + 255) / 256, 256>>>();

    // launch 2: qkv = qkv_w @ x
    tf32_gemm<CC><<<dim3(HWN / TBN, (C3 + TBM - 1) / TBM, NB), 256>>>(
        qkv_w, x, qkv1, C3, HWN,
        0, (size_t)CC * HWN, (size_t)C3 * HWN);

    // launch 3: dwconv
    dwconv_kernel<<<(int)(((size_t)NB * C3 * HWN) / 16 / 256), 256>>>(dw_w);

    // launch 4: gram + sumsq (ncu capture slot)
    gram_kernel<<<dim3(GSPL, NB * NHD), 192>>>();

    attn_kernel<<<2, 192>>>(temp);

    m2_kernel<<<(NB * CC * CC + 255) / 256, 256>>>(proj_w);

    // final: out[b] = M2[b] @ v[b]
    tf32_gemm<CC><<<dim3(HWN / TBN, (CC + TBM - 1) / TBM, NB), 256>>>(
        m2, qkv2 + (size_t)2 * CC * HWN, out, CC, HWN,
        (size_t)CC * CC, (size_t)C3 * HWN, (size_t)CC * HWN);
}